// round 9
// baseline (speedup 1.0000x reference)
#include <cuda_runtime.h>
#include <cuda_fp16.h>

#define NN 100000
#define NE 1600000
#define NB_SCAN 98   // ceil(NN/1024)

// ---- scratch (__device__ globals; no allocations allowed) ----
__device__ __align__(16) float g_dinv[NN];
__device__ __align__(16) __half2 g_h1h[NN * 32];  // UNSCALED layer-1 feats (fp16)
__device__ __align__(16) __half2 g_t1[NN * 32];   // relu(dinv*agg1+b1)  (gemm2 input)
__device__ __align__(16) __half2 g_h2h[NN * 16];  // dinv-scaled layer-2 feats
__device__ __align__(16) __half2 g_t2[NN * 16];
__device__ __align__(16) __half2 g_h3h[NN * 8];   // dinv-scaled layer-3 feats
__device__ int g_degi[NN];
__device__ int g_off[NN + 1];
__device__ int g_cur[NN];
__device__ int g_eidx[NE];
__device__ unsigned long long g_state[128];

__device__ __forceinline__ unsigned h2u(__half2 h) { return *(unsigned*)&h; }
__device__ __forceinline__ float2 u2f(unsigned u) { return __half22float2(*(__half2*)&u); }

// ================= CSR build + dinv =================
__global__ void k_hist(const int* __restrict__ dst) {
    int e = blockIdx.x * blockDim.x + threadIdx.x;
    if (e < NE) atomicAdd(&g_degi[dst[e]], 1);
}

__global__ void __launch_bounds__(1024) k_scan() {
    __shared__ int wsum[32];
    __shared__ int s_prefix;
    const int tid = threadIdx.x, bid = blockIdx.x;
    const int i = bid * 1024 + tid;
    const int lane = tid & 31, w = tid >> 5;
    int deg = (i < NN) ? g_degi[i] : 0;
    int v = deg;
#pragma unroll
    for (int s = 1; s < 32; s <<= 1) {
        int t = __shfl_up_sync(~0u, v, s);
        if (lane >= s) v += t;
    }
    if (lane == 31) wsum[w] = v;
    __syncthreads();
    if (w == 0) {
        int x = wsum[lane];
#pragma unroll
        for (int s = 1; s < 32; s <<= 1) {
            int t = __shfl_up_sync(~0u, x, s);
            if (lane >= s) x += t;
        }
        wsum[lane] = x;
    }
    __syncthreads();
    const int wpre = (w == 0) ? 0 : wsum[w - 1];
    const int excl = wpre + v - deg;
    const int total = wsum[31];

    if (w == 0) {
        if (lane == 0) {
            unsigned long long word =
                ((unsigned long long)(bid == 0 ? 2 : 1) << 32) | (unsigned)total;
            *(volatile unsigned long long*)&g_state[bid] = word;
        }
        if (bid > 0) {
            int run = 0;
            int base = bid - 1;
            while (true) {
                int p = base - lane;
                unsigned long long wd = (p >= 0)
                    ? *(volatile unsigned long long*)&g_state[p]
                    : (2ULL << 32);
                int st = (int)(wd >> 32);
                int val = (int)(wd & 0xffffffffu);
                if (__any_sync(~0u, st == 0)) continue;
                unsigned m2 = __ballot_sync(~0u, st == 2);
                if (m2) {
                    int L = __ffs(m2) - 1;
                    int c = (lane <= L) ? val : 0;
#pragma unroll
                    for (int s = 16; s >= 1; s >>= 1) c += __shfl_xor_sync(~0u, c, s);
                    run += c;
                    break;
                } else {
                    int c = (p >= 0) ? val : 0;
#pragma unroll
                    for (int s = 16; s >= 1; s >>= 1) c += __shfl_xor_sync(~0u, c, s);
                    run += c;
                    base -= 32;
                }
            }
            if (lane == 0) {
                *(volatile unsigned long long*)&g_state[bid] =
                    (2ULL << 32) | (unsigned)(total + run);
                s_prefix = run;
            }
        } else if (lane == 0) {
            s_prefix = 0;
        }
    }
    __syncthreads();
    const int off = excl + s_prefix;
    if (i < NN) {
        g_off[i] = off;
        g_cur[i] = off;
        g_dinv[i] = rsqrtf((float)(1 + deg));
    }
    if (i == 0) g_off[NN] = NE;
}

__global__ void k_fill(const int* __restrict__ src, const int* __restrict__ dst) {
    int e = blockIdx.x * blockDim.x + threadIdx.x;
    if (e < NE) {
        int p = atomicAdd(&g_cur[dst[e]], 1);
        g_eidx[p] = src[e];
    }
}

// ================= GEMM1 (TF32 MMA, cp.async 3-stage; best measured config) =====
__global__ void __launch_bounds__(128) k_gemm1(const float* __restrict__ X,
                                               const float* __restrict__ W) {
    __shared__ unsigned As[3][128 * 20];
    __shared__ unsigned Bs[3][16 * 72];
    const int tid = threadIdx.x;
    const int lane = tid & 31;
    const int w = tid >> 5;
    const int row0 = blockIdx.x * 128;
    const int g = lane >> 2;
    const int tg = lane & 3;

    float c[2][8][4];
#pragma unroll
    for (int mt = 0; mt < 2; mt++)
#pragma unroll
        for (int nt = 0; nt < 8; nt++)
#pragma unroll
            for (int q = 0; q < 4; q++) c[mt][nt][q] = 0.0f;

#define ISSUE(kt, st)                                                            \
    {                                                                            \
        _Pragma("unroll") for (int it = 0; it < 4; it++) {                       \
            int i = it * 128 + tid;                                              \
            int r = i >> 2, kq = i & 3;                                          \
            int gr = row0 + r; if (gr >= NN) gr = NN - 1;                        \
            const float* gp = X + (size_t)gr * 512 + (kt) * 16 + kq * 4;         \
            unsigned sa = (unsigned)__cvta_generic_to_shared(&As[st][r * 20 + kq * 4]); \
            asm volatile("cp.async.cg.shared.global [%0], [%1], 16;" ::          \
                         "r"(sa), "l"(gp));                                      \
        }                                                                        \
        _Pragma("unroll") for (int it = 0; it < 2; it++) {                       \
            int i = it * 128 + tid;                                              \
            int k = i >> 4, n4 = i & 15;                                         \
            const float* gp = W + (size_t)((kt) * 16 + k) * 64 + n4 * 4;         \
            unsigned sa = (unsigned)__cvta_generic_to_shared(&Bs[st][k * 72 + n4 * 4]); \
            asm volatile("cp.async.cg.shared.global [%0], [%1], 16;" ::          \
                         "r"(sa), "l"(gp));                                      \
        }                                                                        \
        asm volatile("cp.async.commit_group;");                                  \
    }

    ISSUE(0, 0);
    ISSUE(1, 1);

    for (int kt = 0; kt < 32; kt++) {
        const int st = kt % 3;
        asm volatile("cp.async.wait_group 1;");
        __syncthreads();
        if (kt + 2 < 32) {
            const int st2 = (kt + 2) % 3;
            ISSUE(kt + 2, st2);
        } else {
            asm volatile("cp.async.commit_group;");
        }
#pragma unroll
        for (int kk = 0; kk < 16; kk += 8) {
            unsigned a[2][4];
#pragma unroll
            for (int mt = 0; mt < 2; mt++) {
                int r = w * 32 + mt * 16 + g;
                a[mt][0] = As[st][r * 20 + kk + tg];
                a[mt][1] = As[st][(r + 8) * 20 + kk + tg];
                a[mt][2] = As[st][r * 20 + kk + tg + 4];
                a[mt][3] = As[st][(r + 8) * 20 + kk + tg + 4];
            }
            unsigned b[8][2];
#pragma unroll
            for (int nt = 0; nt < 8; nt++) {
                int n = nt * 8 + g;
                b[nt][0] = Bs[st][(kk + tg) * 72 + n];
                b[nt][1] = Bs[st][(kk + tg + 4) * 72 + n];
            }
#pragma unroll
            for (int mt = 0; mt < 2; mt++)
#pragma unroll
                for (int nt = 0; nt < 8; nt++)
                    asm volatile(
                        "mma.sync.aligned.m16n8k8.row.col.f32.tf32.tf32.f32 "
                        "{%0,%1,%2,%3}, {%4,%5,%6,%7}, {%8,%9}, {%0,%1,%2,%3};"
                        : "+f"(c[mt][nt][0]), "+f"(c[mt][nt][1]),
                          "+f"(c[mt][nt][2]), "+f"(c[mt][nt][3])
                        : "r"(a[mt][0]), "r"(a[mt][1]), "r"(a[mt][2]), "r"(a[mt][3]),
                          "r"(b[nt][0]), "r"(b[nt][1]));
        }
    }
#undef ISSUE

    // epilogue: store UNSCALED fp16 features
#pragma unroll
    for (int mt = 0; mt < 2; mt++) {
        int r_base = row0 + w * 32 + mt * 16 + g;
#pragma unroll
        for (int half = 0; half < 2; half++) {
            int r = r_base + half * 8;
            if (r < NN) {
#pragma unroll
                for (int nt = 0; nt < 8; nt++) {
                    g_h1h[(size_t)r * 32 + nt * 4 + tg] =
                        __floats2half2_rn(c[mt][nt][half * 2 + 0],
                                          c[mt][nt][half * 2 + 1]);
                }
            }
        }
    }
}

// ================= divergence-free warp-per-node gathers =================
// Layer 1: 64 feats (128B/row). Warp = 1 node; lane = feat pair; unroll 4 edges.
__global__ void __launch_bounds__(256) k_gather64(const float* __restrict__ b1) {
    int n = (blockIdx.x * 256 + threadIdx.x) >> 5;
    int lane = threadIdx.x & 31;
    if (n >= NN) return;
    int j = g_off[n];
    const int e = g_off[n + 1];
    float dvn = g_dinv[n];
    float2 h = u2f(h2u(g_h1h[(size_t)n * 32 + lane]));
    float2 a = make_float2(dvn * h.x, dvn * h.y);
    for (; j + 3 < e; j += 4) {
        int s0 = __ldg(&g_eidx[j]);
        int s1 = __ldg(&g_eidx[j + 1]);
        int s2 = __ldg(&g_eidx[j + 2]);
        int s3 = __ldg(&g_eidx[j + 3]);
        float d0 = __ldg(&g_dinv[s0]), d1 = __ldg(&g_dinv[s1]);
        float d2 = __ldg(&g_dinv[s2]), d3 = __ldg(&g_dinv[s3]);
        float2 u0 = __half22float2(__ldg(&g_h1h[(size_t)s0 * 32 + lane]));
        float2 u1 = __half22float2(__ldg(&g_h1h[(size_t)s1 * 32 + lane]));
        float2 u2 = __half22float2(__ldg(&g_h1h[(size_t)s2 * 32 + lane]));
        float2 u3 = __half22float2(__ldg(&g_h1h[(size_t)s3 * 32 + lane]));
        a.x = fmaf(d0, u0.x, a.x); a.y = fmaf(d0, u0.y, a.y);
        a.x = fmaf(d1, u1.x, a.x); a.y = fmaf(d1, u1.y, a.y);
        a.x = fmaf(d2, u2.x, a.x); a.y = fmaf(d2, u2.y, a.y);
        a.x = fmaf(d3, u3.x, a.x); a.y = fmaf(d3, u3.y, a.y);
    }
    for (; j < e; j++) {
        int s0 = __ldg(&g_eidx[j]);
        float d0 = __ldg(&g_dinv[s0]);
        float2 u0 = __half22float2(__ldg(&g_h1h[(size_t)s0 * 32 + lane]));
        a.x = fmaf(d0, u0.x, a.x); a.y = fmaf(d0, u0.y, a.y);
    }
    float tx = fmaxf(fmaf(a.x, dvn, __ldg(&b1[2 * lane])), 0.0f);
    float ty = fmaxf(fmaf(a.y, dvn, __ldg(&b1[2 * lane + 1])), 0.0f);
    g_t1[(size_t)n * 32 + lane] = __floats2half2_rn(tx, ty);
}
// Layer 2: 32 feats (64B/row). Warp = 1 node; 2 edge slots x 16 lanes; unroll 2.
__global__ void __launch_bounds__(256) k_gather32(const float* __restrict__ b2) {
    int n = (blockIdx.x * 256 + threadIdx.x) >> 5;
    int lane = threadIdx.x & 31;
    if (n >= NN) return;
    const int slot = lane >> 4;   // 0..1
    const int fl = lane & 15;     // feat pair
    int j = g_off[n];
    const int e = g_off[n + 1];
    float2 a = make_float2(0.0f, 0.0f);
    if (slot == 0) a = __half22float2(g_h2h[(size_t)n * 16 + fl]);   // self-loop
    for (; j + 3 < e; j += 4) {
        int sA = __ldg(&g_eidx[j + slot]);
        int sB = __ldg(&g_eidx[j + 2 + slot]);
        float2 uA = __half22float2(__ldg(&g_h2h[(size_t)sA * 16 + fl]));
        float2 uB = __half22float2(__ldg(&g_h2h[(size_t)sB * 16 + fl]));
        a.x += uA.x + uB.x;
        a.y += uA.y + uB.y;
    }
    if (j + 1 < e) {
        int sA = __ldg(&g_eidx[j + slot]);
        float2 uA = __half22float2(__ldg(&g_h2h[(size_t)sA * 16 + fl]));
        a.x += uA.x; a.y += uA.y;
        j += 2;
    }
    if (j < e && slot == 0) {
        int sA = __ldg(&g_eidx[j]);
        float2 uA = __half22float2(__ldg(&g_h2h[(size_t)sA * 16 + fl]));
        a.x += uA.x; a.y += uA.y;
    }
    // reduce across the 2 slots
    a.x += __shfl_xor_sync(0xffffffffu, a.x, 16);
    a.y += __shfl_xor_sync(0xffffffffu, a.y, 16);
    if (slot == 0) {
        float dv = g_dinv[n];
        float tx = fmaxf(fmaf(a.x, dv, __ldg(&b2[2 * fl])), 0.0f);
        float ty = fmaxf(fmaf(a.y, dv, __ldg(&b2[2 * fl + 1])), 0.0f);
        g_t2[(size_t)n * 16 + fl] = __floats2half2_rn(tx, ty);
    }
}
// Layer 3 + log_softmax: 16 feats (32B/row). Warp = 1 node; 4 slots x 8 lanes; unroll 2.
__global__ void __launch_bounds__(256) k_gather16_final(const float* __restrict__ b3,
                                                        float* __restrict__ outv) {
    int n = (blockIdx.x * 256 + threadIdx.x) >> 5;
    int lane = threadIdx.x & 31;
    if (n >= NN) return;
    const int slot = lane >> 3;   // 0..3
    const int fl = lane & 7;      // feat pair
    int j = g_off[n];
    const int e = g_off[n + 1];
    float2 a = make_float2(0.0f, 0.0f);
    if (slot == 0) a = __half22float2(g_h3h[(size_t)n * 8 + fl]);    // self-loop
    for (; j + 7 < e; j += 8) {
        int sA = __ldg(&g_eidx[j + slot]);
        int sB = __ldg(&g_eidx[j + 4 + slot]);
        float2 uA = __half22float2(__ldg(&g_h3h[(size_t)sA * 8 + fl]));
        float2 uB = __half22float2(__ldg(&g_h3h[(size_t)sB * 8 + fl]));
        a.x += uA.x + uB.x;
        a.y += uA.y + uB.y;
    }
    if (j + 3 < e) {
        int sA = __ldg(&g_eidx[j + slot]);
        float2 uA = __half22float2(__ldg(&g_h3h[(size_t)sA * 8 + fl]));
        a.x += uA.x; a.y += uA.y;
        j += 4;
    }
    if (slot < e - j) {   // remainder 0..3 edges
        int sA = __ldg(&g_eidx[j + slot]);
        float2 uA = __half22float2(__ldg(&g_h3h[(size_t)sA * 8 + fl]));
        a.x += uA.x; a.y += uA.y;
    }
    // reduce across the 4 slots
    a.x += __shfl_xor_sync(0xffffffffu, a.x, 8);
    a.y += __shfl_xor_sync(0xffffffffu, a.y, 8);
    a.x += __shfl_xor_sync(0xffffffffu, a.x, 16);
    a.y += __shfl_xor_sync(0xffffffffu, a.y, 16);
    float dv = g_dinv[n];
    float vx = fmaf(a.x, dv, __ldg(&b3[2 * fl]));
    float vy = fmaf(a.y, dv, __ldg(&b3[2 * fl + 1]));
    // log_softmax over the 16 logits held by the 8-lane group
    float m = fmaxf(vx, vy);
#pragma unroll
    for (int s = 4; s >= 1; s >>= 1) m = fmaxf(m, __shfl_xor_sync(0xffffffffu, m, s));
    float su = expf(vx - m) + expf(vy - m);
#pragma unroll
    for (int s = 4; s >= 1; s >>= 1) su += __shfl_xor_sync(0xffffffffu, su, s);
    float lse = m + logf(su);
    if (slot == 0)
        *(float2*)(outv + (size_t)n * 16 + 2 * fl) = make_float2(vx - lse, vy - lse);
}

// ================= small GEMMs (inputs already transformed, fp16) =================
__global__ void __launch_bounds__(256) k_gemm2(const float* __restrict__ W2) {
    __shared__ float Ts[64][68];
    __shared__ float Ws[64 * 32];
    const int tid = threadIdx.x;
    const int row0 = blockIdx.x * 64;
#pragma unroll
    for (int it = 0; it < 2; it++) {
        int i = it * 256 + tid;
        *(float4*)(Ws + i * 4) = *(const float4*)(W2 + i * 4);
    }
#pragma unroll
    for (int it = 0; it < 8; it++) {
        int i = it * 256 + tid;
        int r = i >> 5;
        int cc = i & 31;
        int gr = row0 + r; if (gr >= NN) gr = NN - 1;
        float2 f = __half22float2(__ldg(&g_t1[(size_t)gr * 32 + cc]));
        Ts[r][2 * cc] = f.x;
        Ts[r][2 * cc + 1] = f.y;
    }
    __syncthreads();
    const int r = tid >> 2;
    const int cg = tid & 3;
    float acc[8];
#pragma unroll
    for (int j = 0; j < 8; j++) acc[j] = 0.0f;
#pragma unroll
    for (int k = 0; k < 64; k++) {
        float a = Ts[r][k];
        float4 w0 = *(const float4*)(Ws + k * 32 + cg * 8);
        float4 w1 = *(const float4*)(Ws + k * 32 + cg * 8 + 4);
        acc[0] = fmaf(a, w0.x, acc[0]); acc[1] = fmaf(a, w0.y, acc[1]);
        acc[2] = fmaf(a, w0.z, acc[2]); acc[3] = fmaf(a, w0.w, acc[3]);
        acc[4] = fmaf(a, w1.x, acc[4]); acc[5] = fmaf(a, w1.y, acc[5]);
        acc[6] = fmaf(a, w1.z, acc[6]); acc[7] = fmaf(a, w1.w, acc[7]);
    }
    int gr = row0 + r;
    if (gr < NN) {
        float dv = g_dinv[gr];
#pragma unroll
        for (int q = 0; q < 4; q++)
            g_h2h[(size_t)gr * 16 + cg * 4 + q] =
                __floats2half2_rn(acc[2 * q] * dv, acc[2 * q + 1] * dv);
    }
}

__global__ void __launch_bounds__(256) k_gemm3(const float* __restrict__ W3) {
    __shared__ float Ts[64][36];
    __shared__ float Ws[32 * 16];
    const int tid = threadIdx.x;
    const int row0 = blockIdx.x * 64;
    if (tid < 128) *(float4*)(Ws + tid * 4) = *(const float4*)(W3 + tid * 4);
#pragma unroll
    for (int it = 0; it < 4; it++) {
        int i = it * 256 + tid;
        int r = i >> 4;
        int cc = i & 15;
        int gr = row0 + r; if (gr >= NN) gr = NN - 1;
        float2 f = __half22float2(__ldg(&g_t2[(size_t)gr * 16 + cc]));
        Ts[r][2 * cc] = f.x;
        Ts[r][2 * cc + 1] = f.y;
    }
    __syncthreads();
    const int r = tid >> 2;
    const int cg = tid & 3;
    float acc[4] = {0.0f, 0.0f, 0.0f, 0.0f};
#pragma unroll
    for (int k = 0; k < 32; k++) {
        float a = Ts[r][k];
        float4 w = *(const float4*)(Ws + k * 16 + cg * 4);
        acc[0] = fmaf(a, w.x, acc[0]); acc[1] = fmaf(a, w.y, acc[1]);
        acc[2] = fmaf(a, w.z, acc[2]); acc[3] = fmaf(a, w.w, acc[3]);
    }
    int gr = row0 + r;
    if (gr < NN) {
        float dv = g_dinv[gr];
        g_h3h[(size_t)gr * 8 + cg * 2 + 0] = __floats2half2_rn(acc[0] * dv, acc[1] * dv);
        g_h3h[(size_t)gr * 8 + cg * 2 + 1] = __floats2half2_rn(acc[2] * dv, acc[3] * dv);
    }
}

extern "C" void kernel_launch(void* const* d_in, const int* in_sizes, int n_in,
                              void* d_out, int out_size) {
    const float* x  = (const float*)d_in[0];
    const int*   ei = (const int*)d_in[1];
    const float* W1 = (const float*)d_in[2];
    const float* b1 = (const float*)d_in[3];
    const float* W2 = (const float*)d_in[4];
    const float* b2 = (const float*)d_in[5];
    const float* W3 = (const float*)d_in[6];
    const float* b3 = (const float*)d_in[7];
    float* out = (float*)d_out;
    const int* src = ei;
    const int* dst = ei + NE;

    void* p_deg = nullptr; cudaGetSymbolAddress(&p_deg, g_degi);
    void* p_st  = nullptr; cudaGetSymbolAddress(&p_st, g_state);

    cudaStream_t s2;
    cudaStreamCreateWithFlags(&s2, cudaStreamNonBlocking);
    cudaEvent_t e0, e1;
    cudaEventCreateWithFlags(&e0, cudaEventDisableTiming);
    cudaEventCreateWithFlags(&e1, cudaEventDisableTiming);

    cudaEventRecord(e0, 0);
    cudaStreamWaitEvent(s2, e0, 0);

    // side stream: CSR + dinv
    cudaMemsetAsync(p_deg, 0, NN * sizeof(int), s2);
    cudaMemsetAsync(p_st, 0, 128 * sizeof(unsigned long long), s2);
    k_hist<<<(NE + 255) / 256, 256, 0, s2>>>(dst);
    k_scan<<<NB_SCAN, 1024, 0, s2>>>();
    k_fill<<<(NE + 255) / 256, 256, 0, s2>>>(src, dst);
    cudaEventRecord(e1, s2);

    // main stream: layer-1 GEMM (independent of CSR/dinv)
    k_gemm1<<<(NN + 127) / 128, 128>>>(x, W1);

    cudaStreamWaitEvent(0, e1, 0);

    const int nb = (NN * 32 + 255) / 256;   // warp per node
    k_gather64<<<nb, 256>>>(b1);
    k_gemm2<<<(NN + 63) / 64, 256>>>(W2);
    k_gather32<<<nb, 256>>>(b2);
    k_gemm3<<<(NN + 63) / 64, 256>>>(W3);
    k_gather16_final<<<nb, 256>>>(b3, out);

    cudaStreamDestroy(s2);
    cudaEventDestroy(e0);
    cudaEventDestroy(e1);
}